// round 17
// baseline (speedup 1.0000x reference)
#include <cuda_runtime.h>
#include <math.h>

#define BB    4
#define SSEQ  4096
#define IND   1024
#define OUTD  1024
#define EE    8
#define LSCALE 512.0f
#define TOKB  16
#define GRID  (BB * (SSEQ / TOKB))    // 1024
#define CPB   (SSEQ / TOKB)           // 256 CTAs per batch

// ---- scratch (device globals; allocation is forbidden) ----
__device__ float    g_seg[BB * IND];   // 16 KB : per-batch column sums (zeroed by gater)
__device__ float    g_coef[BB * 2];
__device__ int      g_idx[BB * 2];
__device__ unsigned g_arrive[BB];      // per-batch stage-1 arrivals (reset by gater)
__device__ unsigned g_flag[BB];        // per-batch gating-done flags (reset by last finisher)
__device__ unsigned g_done[BB];        // per-batch stage-2 completion counters

typedef unsigned long long u64;

__device__ __forceinline__ void fma2(u64& d, u64 a, u64 b) {
    asm("fma.rn.f32x2 %0, %1, %2, %0;" : "+l"(d) : "l"(a), "l"(b));
}
__device__ __forceinline__ float lo2(u64 v) { return __uint_as_float((unsigned)(v & 0xffffffffull)); }
__device__ __forceinline__ float hi2(u64 v) { return __uint_as_float((unsigned)(v >> 32)); }

__device__ __forceinline__ void stcs4(float* p, float4 v) {
    asm volatile("st.global.cs.v4.f32 [%0], {%1, %2, %3, %4};"
                 :: "l"(p), "f"(v.x), "f"(v.y), "f"(v.z), "f"(v.w));
}

// ------------------------------------------------------------------
// R15 structure reshaped for 2x warp-parallelism:
//   grid 1024 (16 tokens/CTA), 256 thr, TPW=2, <=48 regs -> 5 CTA/SM.
// Residency note: capacity 740 < 1024 is SAFE — per-batch flags +
// bid-ordered scheduling mean the oldest incomplete batch (256 CTAs
// <= capacity) always becomes fully resident as older batches exit;
// spinners never block the CTAs they wait on.
//   stage 1: column sums of this CTA's 16 rows + REDG + arrive
//   256th arriver of batch b: gating, release flag[b]
//   stage 2: select+project (2 selected dots), proven store loop.
// ------------------------------------------------------------------
#define TPW 2

__global__ void __launch_bounds__(256, 5) fused_moe(const float* __restrict__ x,
                                                    const float* __restrict__ lora_A,
                                                    const float* __restrict__ lora_B,
                                                    const float* __restrict__ gate_w,
                                                    const float* __restrict__ gate_b,
                                                    float* __restrict__ out) {
    __shared__ float    A2[2 * IND];    // 8 KB : selected experts' A rows
    __shared__ float2   cs[TOKB];
    __shared__ float    dots[EE];
    __shared__ unsigned s_last;
    __shared__ int2     s_ix;
    __shared__ float2   s_cf;

    const int tid  = threadIdx.x;
    const int w    = tid >> 5;
    const int lane = tid & 31;
    const int b       = blockIdx.x >> 8;            // 256 CTAs per batch
    const int tokbase = (blockIdx.x & 255) * TOKB;

    // ================= stage 1: column sums (proven loop) ================
    {
        const float* xp = x + ((size_t)b * SSEQ + tokbase) * IND + tid * 4;
        float4 a4 = make_float4(0.f, 0.f, 0.f, 0.f);
        #pragma unroll 8
        for (int r = 0; r < TOKB; ++r) {
            float4 v = *(const float4*)(xp + (size_t)r * IND);
            a4.x += v.x; a4.y += v.y; a4.z += v.z; a4.w += v.w;
        }
        float* dst = &g_seg[b * IND + tid * 4];
        atomicAdd(dst + 0, a4.x);
        atomicAdd(dst + 1, a4.y);
        atomicAdd(dst + 2, a4.z);
        atomicAdd(dst + 3, a4.w);
    }

    // ============ per-batch arrive; 256th arriver gates batch b ==========
    __syncthreads();
    if (tid == 0) {
        unsigned old;
        asm volatile("atom.acq_rel.gpu.global.add.u32 %0, [%1], 1;"
                     : "=r"(old) : "l"(&g_arrive[b]) : "memory");
        s_last = (old == (unsigned)(CPB - 1)) ? 1u : 0u;
    }
    __syncthreads();

    if (s_last) {
        // ---- gating for THIS batch only: warp w owns expert w ----
        {
            float s = 0.f;
            #pragma unroll
            for (int i = 0; i < 8; ++i) {
                int k = lane * 4 + i * 128;
                float4 a = *(const float4*)&g_seg[b * IND + k];
                float4 g = *(const float4*)&gate_w[w * IND + k];
                s += a.x * g.x + a.y * g.y + a.z * g.z + a.w * g.w;
            }
            #pragma unroll
            for (int o = 16; o; o >>= 1) s += __shfl_xor_sync(0xffffffffu, s, o);
            if (lane == 0) dots[w] = s * (1.0f / (float)SSEQ) + gate_b[w];
        }
        __syncthreads();

        // zero this batch's g_seg slice for the next replay (256 float4)
        ((float4*)&g_seg[b * IND])[tid] = make_float4(0.f, 0.f, 0.f, 0.f);

        if (tid == 0) {
            float l[EE]; float mx = -1e30f;
            #pragma unroll
            for (int i = 0; i < EE; ++i) { l[i] = dots[i]; mx = fmaxf(mx, l[i]); }
            float sum = 0.f;
            #pragma unroll
            for (int i = 0; i < EE; ++i) { l[i] = expf(l[i] - mx); sum += l[i]; }
            int i0 = 0;
            #pragma unroll
            for (int i = 1; i < EE; ++i) if (l[i] > l[i0]) i0 = i;   // ties -> lowest idx
            int i1 = (i0 == 0) ? 1 : 0;
            #pragma unroll
            for (int i = 0; i < EE; ++i) if (i != i0 && l[i] > l[i1]) i1 = i;
            g_idx[b * 2] = i0;  g_idx[b * 2 + 1] = i1;
            float f = LSCALE / sum;
            g_coef[b * 2]     = l[i0] * f;
            g_coef[b * 2 + 1] = l[i1] * f;
            g_arrive[b] = 0;                        // safe: all arrived
        }
        __syncthreads();                            // coef/idx + zeroing done
        if (tid == 0)
            asm volatile("st.release.gpu.global.u32 [%0], %1;"
                         :: "l"(&g_flag[b]), "r"(1u) : "memory");
    } else {
        if (tid == 0) {
            unsigned f = 0;
            do {
                __nanosleep(64);
                asm volatile("ld.acquire.gpu.global.u32 %0, [%1];"
                             : "=r"(f) : "l"(&g_flag[b]) : "memory");
            } while (f == 0);
        }
    }
    __syncthreads();

    // broadcast gate results via shared (tid0 holds the acquire edge)
    if (tid == 0) {
        s_ix = *(const int2*)&g_idx[b * 2];
        s_cf = *(const float2*)&g_coef[b * 2];
    }
    __syncthreads();
    const int   e0 = s_ix.x, e1 = s_ix.y;
    const float w0 = s_cf.x, w1 = s_cf.y;

    // ================= stage 2: select + project (R15-proven) ============
    {
        float4 a0 = *(const float4*)&lora_A[e0 * IND + tid * 4];
        float4 a1 = *(const float4*)&lora_A[e1 * IND + tid * 4];
        *(float4*)&A2[tid * 4]       = a0;
        *(float4*)&A2[IND + tid * 4] = a1;
    }
    __syncthreads();

    u64 acc0[TPW], acc1[TPW];
    #pragma unroll
    for (int t = 0; t < TPW; ++t) { acc0[t] = 0ull; acc1[t] = 0ull; }

    const float* xw = x + ((size_t)(b * SSEQ + tokbase + w * TPW)) * IND;

    #pragma unroll 2
    for (int c = 0; c < 8; ++c) {
        const int koff = c * 128 + lane * 4;
        double2 a0v = *(const double2*)&A2[koff];
        double2 a1v = *(const double2*)&A2[IND + koff];
        u64 a0lo = __double_as_longlong(a0v.x), a0hi = __double_as_longlong(a0v.y);
        u64 a1lo = __double_as_longlong(a1v.x), a1hi = __double_as_longlong(a1v.y);
        #pragma unroll
        for (int t = 0; t < TPW; ++t) {
            double2 xv = *(const double2*)(xw + (size_t)t * IND + koff);
            u64 xlo = __double_as_longlong(xv.x);
            u64 xhi = __double_as_longlong(xv.y);
            fma2(acc0[t], xlo, a0lo);
            fma2(acc0[t], xhi, a0hi);
            fma2(acc1[t], xlo, a1lo);
            fma2(acc1[t], xhi, a1hi);
        }
    }

    #pragma unroll
    for (int t = 0; t < TPW; ++t) {
        float h0 = lo2(acc0[t]) + hi2(acc0[t]);
        float h1 = lo2(acc1[t]) + hi2(acc1[t]);
        #pragma unroll
        for (int off = 16; off; off >>= 1) {
            h0 += __shfl_xor_sync(0xffffffffu, h0, off);
            h1 += __shfl_xor_sync(0xffffffffu, h1, off);
        }
        if (lane == 0) cs[w * TPW + t] = make_float2(w0 * h0, w1 * h1);
    }

    // B rows register-resident — loaded after phase A
    float4 B0 = *(const float4*)&lora_B[e0 * OUTD + tid * 4];
    float4 B1 = *(const float4*)&lora_B[e1 * OUTD + tid * 4];
    __syncthreads();

    float* ob = out + ((size_t)b * SSEQ + tokbase) * OUTD + tid * 4;
    #pragma unroll 4
    for (int i = 0; i < TOKB; ++i) {
        float2 cc = cs[i];
        float4 v;
        v.x = cc.x * B0.x + cc.y * B1.x;
        v.y = cc.x * B0.y + cc.y * B1.y;
        v.z = cc.x * B0.z + cc.y * B1.z;
        v.w = cc.x * B0.w + cc.y * B1.w;
        stcs4(ob + (size_t)i * OUTD, v);
    }

    // ---- per-batch flag reset for the next graph replay ----
    __syncthreads();
    if (tid == 0) {
        unsigned old;
        asm volatile("atom.acq_rel.gpu.global.add.u32 %0, [%1], 1;"
                     : "=r"(old) : "l"(&g_done[b]) : "memory");
        if (old == (unsigned)(CPB - 1)) {
            g_flag[b] = 0;
            g_done[b] = 0;
        }
    }
}

// ------------------------------------------------------------------
extern "C" void kernel_launch(void* const* d_in, const int* in_sizes, int n_in,
                              void* d_out, int out_size) {
    const float* x      = (const float*)d_in[0];
    const float* lora_A = (const float*)d_in[1];
    const float* lora_B = (const float*)d_in[2];
    const float* gate_w = (const float*)d_in[3];
    const float* gate_b = (const float*)d_in[4];
    float* out = (float*)d_out;

    fused_moe<<<GRID, 256>>>(x, lora_A, lora_B, gate_w, gate_b, out);
}